// round 13
// baseline (speedup 1.0000x reference)
#include <cuda_runtime.h>
#include <cuda_bf16.h>
#include <cuda_fp16.h>
#include <cstdint>

#define BB 4
#define TT 4096
#define CC 1024
#define HH 64
constexpr int MROWS = BB * TT;  // 16384

// ---------------- device scratch (q scaled by 1/32) ----------------
__device__ __nv_bfloat16 g_wth[192 * CC], g_wtl[192 * CC];   // W^T hi/lo [n][c]
__device__ __half g_q[MROWS * HH];   // q/32, fp16
__device__ __half g_k[MROWS * HH];   // k, fp16
__device__ __half g_v[MROWS * HH];   // v, fp16
// split-KV partials: 256 q-tiles x up to 4 chunks of 16 k-tiles
__device__ float g_po[1024 * 64 * 64];
__device__ float g_pm[1024 * 64];
__device__ float g_pl[1024 * 64];

// ---------------- helpers ----------------
__device__ __forceinline__ uint32_t smem_u32(const void* p) {
    uint32_t a;
    asm("{ .reg .u64 t; cvta.to.shared.u64 t, %1; cvt.u32.u64 %0, t; }" : "=r"(a) : "l"(p));
    return a;
}
__device__ __forceinline__ uint32_t pkbf(float lo, float hi) {  // bf16x2 {lo,hi}
    uint32_t d;
    asm("cvt.rn.bf16x2.f32 %0, %1, %2;" : "=r"(d) : "f"(hi), "f"(lo));
    return d;
}
__device__ __forceinline__ uint32_t pkhf(float lo, float hi) {  // f16x2 {lo,hi}
    uint32_t d;
    asm("cvt.rn.f16x2.f32 %0, %1, %2;" : "=r"(d) : "f"(hi), "f"(lo));
    return d;
}
__device__ __forceinline__ float bfr(float x) { return __bfloat162float(__float2bfloat16_rn(x)); }
__device__ __forceinline__ float ex2f(float x) {
    float r; asm("ex2.approx.ftz.f32 %0, %1;" : "=f"(r) : "f"(x)); return r;
}
__device__ __forceinline__ void ldsm4(uint4& d, uint32_t a) {
    asm volatile("ldmatrix.sync.aligned.m8n8.x4.shared.b16 {%0,%1,%2,%3}, [%4];"
                 : "=r"(d.x), "=r"(d.y), "=r"(d.z), "=r"(d.w) : "r"(a));
}
__device__ __forceinline__ void ldsm4t(uint4& d, uint32_t a) {
    asm volatile("ldmatrix.sync.aligned.m8n8.x4.trans.shared.b16 {%0,%1,%2,%3}, [%4];"
                 : "=r"(d.x), "=r"(d.y), "=r"(d.z), "=r"(d.w) : "r"(a));
}
__device__ __forceinline__ void mmabf(float* c, const uint4& a, uint32_t b0, uint32_t b1) {
    asm volatile("mma.sync.aligned.m16n8k16.row.col.f32.bf16.bf16.f32 "
                 "{%0,%1,%2,%3}, {%4,%5,%6,%7}, {%8,%9}, {%0,%1,%2,%3};"
                 : "+f"(c[0]), "+f"(c[1]), "+f"(c[2]), "+f"(c[3])
                 : "r"(a.x), "r"(a.y), "r"(a.z), "r"(a.w), "r"(b0), "r"(b1));
}
__device__ __forceinline__ void mmahf(float* c, const uint4& a, uint32_t b0, uint32_t b1) {
    asm volatile("mma.sync.aligned.m16n8k16.row.col.f32.f16.f16.f32 "
                 "{%0,%1,%2,%3}, {%4,%5,%6,%7}, {%8,%9}, {%0,%1,%2,%3};"
                 : "+f"(c[0]), "+f"(c[1]), "+f"(c[2]), "+f"(c[3])
                 : "r"(a.x), "r"(a.y), "r"(a.z), "r"(a.w), "r"(b0), "r"(b1));
}
__device__ __forceinline__ void mmahf_a(float* c, uint32_t a0, uint32_t a1, uint32_t a2,
                                        uint32_t a3, uint32_t b0, uint32_t b1) {
    asm volatile("mma.sync.aligned.m16n8k16.row.col.f32.f16.f16.f32 "
                 "{%0,%1,%2,%3}, {%4,%5,%6,%7}, {%8,%9}, {%0,%1,%2,%3};"
                 : "+f"(c[0]), "+f"(c[1]), "+f"(c[2]), "+f"(c[3])
                 : "r"(a0), "r"(a1), "r"(a2), "r"(a3), "r"(b0), "r"(b1));
}
#define CPA(dst, src)  asm volatile("cp.async.cg.shared.global [%0], [%1], 16;" :: "r"(dst), "l"(src))
#define CPCOMMIT()     asm volatile("cp.async.commit_group;" ::: "memory")
#define CPWAIT0()      asm volatile("cp.async.wait_group 0;" ::: "memory")

// ---------------------------------------------------------------------------
// Kernel 0: W^T hi/lo split (coalesced via smem transpose).
// ---------------------------------------------------------------------------
__global__ __launch_bounds__(256) void prep_kernel(
    const float* __restrict__ Wq, const float* __restrict__ Wk,
    const float* __restrict__ Wv) {
    __shared__ float s[8][1032];
    const int tid = threadIdx.x;
    const int n0 = blockIdx.x * 8;
    const float* W = (n0 < 64) ? Wq : ((n0 < 128) ? Wk : Wv);
    const int col0 = n0 & 63;
    const int nn = tid & 7, cc = tid >> 3;
    for (int c0 = 0; c0 < CC; c0 += 32)
        s[nn][c0 + cc] = W[(c0 + cc) * 64 + col0 + nn];
    __syncthreads();
    const int row = tid >> 5, lane = tid & 31;
    const int n = n0 + row;
    const float* sr = s[row];
    uint32_t* dh = (uint32_t*)g_wth + (size_t)n * 512;
    uint32_t* dl = (uint32_t*)g_wtl + (size_t)n * 512;
#pragma unroll
    for (int k = 0; k < 16; k++) {
        int c = 2 * lane + 64 * k;
        float a0 = sr[c], a1 = sr[c + 1];
        dh[lane + 32 * k] = pkbf(a0, a1);
        dl[lane + 32 * k] = pkbf(a0 - bfr(a0), a1 - bfr(a1));
    }
}

// ---------------------------------------------------------------------------
// Kernel 1: QKV projection.  Block tile 128(M) x 96(N), grid (128, 2).
// A single-buffered (36864), B double-buffered (2 x 27648) => 92160 B smem,
// 2 CTAs/SM.  8 warps = 4(M) x 2(N, 48 cols each).  bf16 3-term (precise).
// ---------------------------------------------------------------------------
#define PRJ_BOFF 36864
#define PRJ_BSTG 27648
#define PRJ_SMEM (PRJ_BOFF + 2 * PRJ_BSTG)   // 92160

__global__ __launch_bounds__(256, 2) void proj_kernel(const float* __restrict__ x) {
    extern __shared__ char sm[];
    uint32_t sb = smem_u32(sm);
    const int tid = threadIdx.x;
    const int lane = tid & 31, wid = tid >> 5;
    const int wm = wid & 3, wn = wid >> 2;
    const int row0 = blockIdx.x * 128;
    const int ny = blockIdx.y;            // 0: n 0..95, 1: n 96..191
    const int arow = tid >> 1, acs = (tid & 1) * 32;

    float c[2][6][4];
#pragma unroll
    for (int i = 0; i < 2; i++)
#pragma unroll
        for (int t = 0; t < 6; t++)
#pragma unroll
            for (int e = 0; e < 4; e++) c[i][t][e] = 0.f;

    float4 xr[8];
    {
        const float4* s = (const float4*)(x + (size_t)(row0 + arow) * CC + acs);
#pragma unroll
        for (int g = 0; g < 8; g++) xr[g] = s[g];
    }
    // B chunk 0 -> stage 0
    {
        uint32_t Bb = sb + PRJ_BOFF;
#pragma unroll
        for (int e = 0; e < 6; e++) {
            int idx = tid + (e % 3) * 256;
            int row = idx >> 3, j = idx & 7;
            const char* src = (e < 3 ? (const char*)g_wth : (const char*)g_wtl)
                              + (size_t)(ny * 96 + row) * 2048 + j * 16;
            CPA(Bb + (e < 3 ? 0u : 13824u) + row * 144 + j * 16, src);
        }
        CPCOMMIT();
    }

    for (int kc = 0; kc < 16; kc++) {
        const uint32_t Ab = sb;
        const uint32_t Bb = sb + PRJ_BOFF + (kc & 1) * PRJ_BSTG;
        __syncthreads();  // prev mma done reading A
        {
            char* dst = sm + arow * 144 + acs * 2;
#pragma unroll
            for (int g = 0; g < 4; g++) {
                float e[8] = {xr[2 * g].x, xr[2 * g].y, xr[2 * g].z, xr[2 * g].w,
                              xr[2 * g + 1].x, xr[2 * g + 1].y, xr[2 * g + 1].z, xr[2 * g + 1].w};
                uint4 H, L;
                uint32_t* hp = (uint32_t*)&H;
                uint32_t* lp = (uint32_t*)&L;
#pragma unroll
                for (int q = 0; q < 4; q++) {
                    float a0 = e[2 * q], a1 = e[2 * q + 1];
                    hp[q] = pkbf(a0, a1);
                    lp[q] = pkbf(a0 - bfr(a0), a1 - bfr(a1));
                }
                *(uint4*)(dst + g * 16) = H;
                *(uint4*)(dst + 18432 + g * 16) = L;
            }
        }
        if (kc < 15) {
            const float4* s = (const float4*)(x + (size_t)(row0 + arow) * CC + (kc + 1) * 64 + acs);
#pragma unroll
            for (int g = 0; g < 8; g++) xr[g] = s[g];
        }
        CPWAIT0();
        __syncthreads();  // A visible + B(kc) ready
        if (kc < 15) {
            uint32_t Bn = sb + PRJ_BOFF + ((kc + 1) & 1) * PRJ_BSTG;
            int k0 = (kc + 1) * 64;
#pragma unroll
            for (int e = 0; e < 6; e++) {
                int idx = tid + (e % 3) * 256;
                int row = idx >> 3, j = idx & 7;
                const char* src = (e < 3 ? (const char*)g_wth : (const char*)g_wtl)
                                  + (size_t)(ny * 96 + row) * 2048 + k0 * 2 + j * 16;
                CPA(Bn + (e < 3 ? 0u : 13824u) + row * 144 + j * 16, src);
            }
            CPCOMMIT();
        }
#pragma unroll
        for (int ks = 0; ks < 4; ks++) {
            uint4 ah[2], al[2];
#pragma unroll
            for (int i = 0; i < 2; i++) {
                uint32_t r = wm * 32 + i * 16 + (lane & 15);
                uint32_t cb = ks * 32 + (lane >> 4) * 16;
                ldsm4(ah[i], Ab + r * 144 + cb);
                ldsm4(al[i], Ab + 18432 + r * 144 + cb);
            }
#pragma unroll
            for (int np = 0; np < 3; np++) {
                uint32_t rn = wn * 48 + np * 16 + (lane & 7) + ((lane >> 4) << 3);
                uint32_t cb = ks * 32 + ((lane >> 3) & 1) * 16;
                uint4 bh, bl;
                ldsm4(bh, Bb + rn * 144 + cb);
                ldsm4(bl, Bb + 13824 + rn * 144 + cb);
#pragma unroll
                for (int i = 0; i < 2; i++) {
                    mmabf(c[i][np * 2], ah[i], bh.x, bh.y);
                    mmabf(c[i][np * 2 + 1], ah[i], bh.z, bh.w);
                    mmabf(c[i][np * 2], al[i], bh.x, bh.y);
                    mmabf(c[i][np * 2 + 1], al[i], bh.z, bh.w);
                    mmabf(c[i][np * 2], ah[i], bl.x, bl.y);
                    mmabf(c[i][np * 2 + 1], ah[i], bl.z, bl.w);
                }
            }
        }
    }
    // epilogue: q (fp16, x1/32), k (fp16), v (fp16)
#pragma unroll
    for (int i = 0; i < 2; i++) {
#pragma unroll
        for (int nt = 0; nt < 6; nt++) {
            int n = ny * 96 + wn * 48 + nt * 8 + (lane & 3) * 2;
            int tgt = n >> 6, nn = n & 63;
            float sc = (tgt == 0) ? 0.03125f : 1.0f;
            uint32_t* dst = (uint32_t*)((tgt == 0) ? g_q : (tgt == 1) ? g_k : g_v);
#pragma unroll
            for (int h = 0; h < 2; h++) {
                int m = row0 + wm * 32 + i * 16 + (lane >> 2) + h * 8;
                float a0 = c[i][nt][2 * h] * sc, a1 = c[i][nt][2 * h + 1] * sc;
                dst[(size_t)m * 32 + nn / 2] = pkhf(a0, a1);
            }
        }
    }
}

// ---------------------------------------------------------------------------
// Kernel 2: flash attention, split-KV chunks of 16 k-tiles.
// BQ=BK=64, 4 warps.  All operands single fp16: QK 1-term, PV 1-term.
// smem stage = K 9216 | V 9216 = 18432, 2 stages = 36864.
// grid 1024: g=bid>>2 -> (qi desc, b), c=bid&3.
// ---------------------------------------------------------------------------
#define ATN_STG 18432
#define ATN_SMEM (2 * ATN_STG)

__global__ __launch_bounds__(128, 4) void attn_kernel() {
    extern __shared__ char sm[];
    uint32_t sb = smem_u32(sm);
    const int tid = threadIdx.x;
    const int lane = tid & 31, wid = tid >> 5;
    const int bid = blockIdx.x;
    const int g = bid >> 2;
    const int qq = 63 - (g >> 2);
    const int b = g & 3;
    const int ch = bid & 3;
    const int nk = qq + 1;
    const int kt0 = ch * 16;
    const int kt1 = (kt0 + 16 < nk) ? kt0 + 16 : nk;
    if (kt0 >= nk) return;  // empty chunk (never read by merge)
    const int pidx = (((b << 6) | qq) << 2) | ch;
    const int pbase = pidx * 4096;
    const float L2E = 1.4426950408889634f;

    // stage Q (64x64 fp16) into stage-0 K slot, load frags, then release
    {
#pragma unroll
        for (int e = 0; e < 4; e++) {
            int idx = tid + e * 128;
            int row = idx >> 3, j = idx & 7;
            const char* src = (const char*)g_q
                              + ((size_t)(b * TT + qq * 64 + row)) * 128 + j * 16;
            CPA(sb + row * 144 + j * 16, src);
        }
        CPCOMMIT();
        CPWAIT0();
        __syncthreads();
    }
    uint4 qf[4];
#pragma unroll
    for (int ks = 0; ks < 4; ks++) {
        uint32_t r = wid * 16 + (lane & 15);
        uint32_t cb = ks * 32 + (lane >> 4) * 16;
        ldsm4(qf[ks], sb + r * 144 + cb);
    }
    __syncthreads();

    // prefetch K/V tile kt0
#pragma unroll
    for (int e = 0; e < 8; e++) {
        int arr = e >> 2;   // 0=K, 1=V
        int idx = tid + (e & 3) * 128;
        int row = idx >> 3, j = idx & 7;
        const char* src = (arr == 0 ? (const char*)g_k : (const char*)g_v)
                          + ((size_t)(b * TT + kt0 * 64 + row)) * 128 + j * 16;
        CPA(sb + (kt0 & 1) * ATN_STG + arr * 9216 + row * 144 + j * 16, src);
    }
    CPCOMMIT();

    float o[8][4];
#pragma unroll
    for (int t = 0; t < 8; t++)
#pragma unroll
        for (int e = 0; e < 4; e++) o[t][e] = 0.f;
    float m0 = -1e30f, m1 = -1e30f, l0 = 0.f, l1 = 0.f;

    const int r0 = wid * 16 + (lane >> 2);
    const int gr0 = qq * 64 + r0;

    for (int kt = kt0; kt < kt1; kt++) {
        CPWAIT0();
        __syncthreads();
        const uint32_t Kb = sb + (kt & 1) * ATN_STG;
        if (kt + 1 < kt1) {
            uint32_t Nb = sb + ((kt + 1) & 1) * ATN_STG;
#pragma unroll
            for (int e = 0; e < 8; e++) {
                int arr = e >> 2;
                int idx = tid + (e & 3) * 128;
                int row = idx >> 3, j = idx & 7;
                const char* src = (arr == 0 ? (const char*)g_k : (const char*)g_v)
                                  + ((size_t)(b * TT + (kt + 1) * 64 + row)) * 128 + j * 16;
                CPA(Nb + arr * 9216 + row * 144 + j * 16, src);
            }
            CPCOMMIT();
        }

        // ---- S = Q K^T (fp16 single-term) ----
        float sc[8][4];
#pragma unroll
        for (int t = 0; t < 8; t++)
#pragma unroll
            for (int e = 0; e < 4; e++) sc[t][e] = 0.f;
#pragma unroll
        for (int ks = 0; ks < 4; ks++) {
#pragma unroll
            for (int np = 0; np < 4; np++) {
                uint32_t rn = np * 16 + (lane & 7) + ((lane >> 4) << 3);
                uint32_t cb = ks * 32 + ((lane >> 3) & 1) * 16;
                uint4 kf;
                ldsm4(kf, Kb + rn * 144 + cb);
                mmahf(sc[np * 2], qf[ks], kf.x, kf.y);
                mmahf(sc[np * 2 + 1], qf[ks], kf.z, kf.w);
            }
        }
        if (kt == qq) {
#pragma unroll
            for (int nt = 0; nt < 8; nt++) {
                int gc = kt * 64 + nt * 8 + (lane & 3) * 2;
                if (gc > gr0) sc[nt][0] = -1e30f;
                if (gc + 1 > gr0) sc[nt][1] = -1e30f;
                if (gc > gr0 + 8) sc[nt][2] = -1e30f;
                if (gc + 1 > gr0 + 8) sc[nt][3] = -1e30f;
            }
        }
        float mt0 = -1e30f, mt1 = -1e30f;
#pragma unroll
        for (int nt = 0; nt < 8; nt++) {
            mt0 = fmaxf(mt0, fmaxf(sc[nt][0], sc[nt][1]));
            mt1 = fmaxf(mt1, fmaxf(sc[nt][2], sc[nt][3]));
        }
        mt0 = fmaxf(mt0, __shfl_xor_sync(0xffffffffu, mt0, 1));
        mt0 = fmaxf(mt0, __shfl_xor_sync(0xffffffffu, mt0, 2));
        mt1 = fmaxf(mt1, __shfl_xor_sync(0xffffffffu, mt1, 1));
        mt1 = fmaxf(mt1, __shfl_xor_sync(0xffffffffu, mt1, 2));
        float mn0 = fmaxf(m0, mt0), mn1 = fmaxf(m1, mt1);
        float al0 = ex2f((m0 - mn0) * L2E), al1 = ex2f((m1 - mn1) * L2E);
        float s0 = 0.f, s1 = 0.f;
#pragma unroll
        for (int nt = 0; nt < 8; nt++) {
            sc[nt][0] = ex2f((sc[nt][0] - mn0) * L2E);
            sc[nt][1] = ex2f((sc[nt][1] - mn0) * L2E);
            sc[nt][2] = ex2f((sc[nt][2] - mn1) * L2E);
            sc[nt][3] = ex2f((sc[nt][3] - mn1) * L2E);
            s0 += sc[nt][0] + sc[nt][1];
            s1 += sc[nt][2] + sc[nt][3];
        }
        s0 += __shfl_xor_sync(0xffffffffu, s0, 1);
        s0 += __shfl_xor_sync(0xffffffffu, s0, 2);
        s1 += __shfl_xor_sync(0xffffffffu, s1, 1);
        s1 += __shfl_xor_sync(0xffffffffu, s1, 2);
        l0 = l0 * al0 + s0; l1 = l1 * al1 + s1;
        m0 = mn0; m1 = mn1;
#pragma unroll
        for (int nt = 0; nt < 8; nt++) {
            o[nt][0] *= al0; o[nt][1] *= al0;
            o[nt][2] *= al1; o[nt][3] *= al1;
        }
        // ---- O += P V (fp16 single-term) ----
#pragma unroll
        for (int sk = 0; sk < 4; sk++) {
            float* t0 = sc[2 * sk];
            float* t1 = sc[2 * sk + 1];
            uint32_t pa0 = pkhf(t0[0], t0[1]), pa1 = pkhf(t0[2], t0[3]);
            uint32_t pa2 = pkhf(t1[0], t1[1]), pa3 = pkhf(t1[2], t1[3]);
#pragma unroll
            for (int hp = 0; hp < 4; hp++) {
                uint32_t rs = sk * 16 + (lane & 7) + ((lane >> 3) & 1) * 8;
                uint32_t hb = (hp * 16 + (lane >> 4) * 8) * 2;
                uint4 v;
                ldsm4t(v, Kb + 9216 + rs * 144 + hb);
                mmahf_a(o[hp * 2], pa0, pa1, pa2, pa3, v.x, v.y);
                mmahf_a(o[hp * 2 + 1], pa0, pa1, pa2, pa3, v.z, v.w);
            }
        }
    }
    // ---- write partials ----
#pragma unroll
    for (int nt = 0; nt < 8; nt++) {
        int col = nt * 8 + (lane & 3) * 2;
        *(float2*)(g_po + pbase + r0 * 64 + col) = make_float2(o[nt][0], o[nt][1]);
        *(float2*)(g_po + pbase + (r0 + 8) * 64 + col) = make_float2(o[nt][2], o[nt][3]);
    }
    if ((lane & 3) == 0) {
        g_pm[pidx * 64 + r0] = m0;     g_pl[pidx * 64 + r0] = l0;
        g_pm[pidx * 64 + r0 + 8] = m1; g_pl[pidx * 64 + r0 + 8] = l1;
    }
}

// ---------------------------------------------------------------------------
// Kernel 3: merge up to 4 chunk partials per q-tile, normalize, write output.
// ---------------------------------------------------------------------------
__global__ __launch_bounds__(256) void merge_kernel(float* __restrict__ out) {
    const int qt = blockIdx.x;           // (b<<6)|qi
    const int b = qt >> 6, qi = qt & 63;
    const int nc = (qi >> 4) + 1;        // chunks of 16 k-tiles
    const int tid = threadIdx.x;
    const int r = tid >> 2, seg = (tid & 3) * 16;
    const float L2E = 1.4426950408889634f;

    float m = -1e30f;
    for (int c = 0; c < nc; c++)
        m = fmaxf(m, g_pm[(qt * 4 + c) * 64 + r]);
    float w[4];
    float lsum = 0.f;
    for (int c = 0; c < nc; c++) {
        w[c] = ex2f((g_pm[(qt * 4 + c) * 64 + r] - m) * L2E);
        lsum += g_pl[(qt * 4 + c) * 64 + r] * w[c];
    }
    float inv = 1.f / lsum;
    float4 acc[4];
#pragma unroll
    for (int gq = 0; gq < 4; gq++) acc[gq] = make_float4(0.f, 0.f, 0.f, 0.f);
    for (int c = 0; c < nc; c++) {
        const float4* oc = (const float4*)(g_po + (qt * 4 + c) * 4096 + r * 64 + seg);
        float wc = w[c];
#pragma unroll
        for (int gq = 0; gq < 4; gq++) {
            float4 v = oc[gq];
            acc[gq].x += v.x * wc; acc[gq].y += v.y * wc;
            acc[gq].z += v.z * wc; acc[gq].w += v.w * wc;
        }
    }
    float4* dst = (float4*)(out + ((size_t)b * TT + qi * 64 + r) * 64 + seg);
#pragma unroll
    for (int gq = 0; gq < 4; gq++) {
        float4 v;
        v.x = acc[gq].x * inv; v.y = acc[gq].y * inv;
        v.z = acc[gq].z * inv; v.w = acc[gq].w * inv;
        dst[gq] = v;
    }
}

// ---------------------------------------------------------------------------
extern "C" void kernel_launch(void* const* d_in, const int* in_sizes, int n_in,
                              void* d_out, int out_size) {
    const float* x  = (const float*)d_in[0];
    const float* Wq = (const float*)d_in[1];
    const float* Wk = (const float*)d_in[2];
    const float* Wv = (const float*)d_in[3];
    float* out = (float*)d_out;

    cudaFuncSetAttribute(proj_kernel, cudaFuncAttributeMaxDynamicSharedMemorySize, PRJ_SMEM);
    cudaFuncSetAttribute(attn_kernel, cudaFuncAttributeMaxDynamicSharedMemorySize, ATN_SMEM);

    prep_kernel<<<24, 256>>>(Wq, Wk, Wv);
    proj_kernel<<<dim3(128, 2), 256, PRJ_SMEM>>>(x);
    attn_kernel<<<1024, 128, ATN_SMEM>>>();
    merge_kernel<<<256, 256>>>(out);
}